// round 5
// baseline (speedup 1.0000x reference)
#include <cuda_runtime.h>
#include <cuda_bf16.h>
#include <math.h>

#define NMAX   100000
#define NSTR   100096     // node stride for transposed buffer (mult of 128)
#define EMAX   1000000
#define HDIM   64
#define NGRAPH 128
#define NCLS   5

typedef unsigned long long u64;

// ---------------- scratch (device globals; never passed from host) ----------------
__device__ int    g_deg[NMAX];
__device__ int    g_cursor[NMAX];
__device__ int    g_off[NMAX + 1];          // +1 sentinel
__device__ int    g_flag[128];
__device__ int    g_poolctr;
__device__ float  g_dinv[NMAX];
__device__ int    g_csrc[EMAX];             // src only (4B/edge)
__device__ __align__(16) float  g_xs[NMAX * 2];     // dinv-prescaled input x
__device__ __align__(16) float4 g_ax4[NMAX];        // {(Ax).x, (Ax).y, dinv, 0}
__device__ __align__(16) float  g_bufA[HDIM * NSTR];// t2 transposed [c][node]; later h3 row-major
__device__ __align__(16) __nv_bfloat16 g_bufBh[NMAX * HDIM]; // dinv-prescaled g2, bf16
__device__ __align__(16) float  g_pooled[NGRAPH * HDIM];

// ---------------- packed helpers ----------------
__device__ __forceinline__ u64 pack2(float a, float b) {
    u64 r; asm("mov.b64 %0, {%1, %2};" : "=l"(r) : "f"(a), "f"(b)); return r;
}
__device__ __forceinline__ void unpack2(u64 v, float& a, float& b) {
    asm("mov.b64 {%0, %1}, %2;" : "=f"(a), "=f"(b) : "l"(v));
}
__device__ __forceinline__ void fma2(u64& d, u64 a, u64 b, u64 c) {
    asm("fma.rn.f32x2 %0, %1, %2, %3;" : "=l"(d) : "l"(a), "l"(b), "l"(c));
}
__device__ __forceinline__ unsigned bf16pack(float lo, float hi) {
    unsigned r; asm("cvt.rn.bf16x2.f32 %0, %1, %2;" : "=r"(r) : "f"(hi), "f"(lo)); return r;
}

// ---------------- CSR build ----------------
__global__ void k_zero(int n) {
    int i = blockIdx.x * blockDim.x + threadIdx.x;
    if (i < n) g_deg[i] = 0;
    if (i < 128) g_flag[i] = 0;
}

__global__ void k_count(const int* __restrict__ dst, int e) {
    int i = blockIdx.x * blockDim.x + threadIdx.x;
    if (i < e) atomicAdd(&g_deg[dst[i]], 1);
}

// single-pass exclusive scan of deg -> off (decoupled lookback).
// also: dinv, cursor=off copy, prescaled xs = dinv*x, off[n] sentinel.
__global__ void k_scan(const float* __restrict__ x, int n) {
    int b = blockIdx.x;
    int i = (b << 10) + threadIdx.x;
    int v = (i < n) ? g_deg[i] : 0;
    float dv = rsqrtf((float)(v + 1));                  // +1 self-loop
    if (i < n) {
        g_dinv[i] = dv;
        float2 xv = *(const float2*)(x + 2 * i);
        g_xs[2 * i]     = dv * xv.x;
        g_xs[2 * i + 1] = dv * xv.y;
    }
    int lane = threadIdx.x & 31, wid = threadIdx.x >> 5;
    int xacc = v;
    #pragma unroll
    for (int o = 1; o < 32; o <<= 1) {
        int y = __shfl_up_sync(0xffffffffu, xacc, o);
        if (lane >= o) xacc += y;
    }
    __shared__ int ws[32];
    __shared__ int s_prefix;
    if (lane == 31) ws[wid] = xacc;
    __syncthreads();
    if (wid == 0) {
        int s = ws[lane];
        #pragma unroll
        for (int o = 1; o < 32; o <<= 1) {
            int y = __shfl_up_sync(0xffffffffu, s, o);
            if (lane >= o) s += y;
        }
        ws[lane] = s;
    }
    __syncthreads();
    int warpoff = (wid == 0) ? 0 : ws[wid - 1];
    int total = ws[31];
    if (threadIdx.x == 0) atomicExch(&g_flag[b], (int)(0x80000000u | (unsigned)total));
    if (threadIdx.x < 32) {
        int sum = 0;
        for (int p = b - 1 - (int)threadIdx.x; p >= 0; p -= 32) {
            int f;
            do { f = atomicAdd(&g_flag[p], 0); } while (f >= 0);
            sum += f & 0x7fffffff;
        }
        #pragma unroll
        for (int o = 16; o; o >>= 1) sum += __shfl_xor_sync(0xffffffffu, sum, o);
        if (threadIdx.x == 0) s_prefix = sum;
    }
    __syncthreads();
    if (i < n) {
        int off = s_prefix + warpoff + xacc - v;        // exclusive
        g_off[i] = off;
        g_cursor[i] = off;
        if (i == n - 1) g_off[n] = s_prefix + warpoff + xacc;  // inclusive = E total
    }
}

// lean scatter: only src index stored; cursor was pre-initialized to off
__global__ void k_scatter(const int* __restrict__ ei, int e) {
    int i = blockIdx.x * blockDim.x + threadIdx.x;
    if (i >= e) return;
    int s = ei[i];
    int d = ei[e + i];
    int p = atomicAdd(&g_cursor[d], 1);
    g_csrc[p] = s;
}

// ---------------- layer 1: plain gather-sum of prescaled xs ----------------
__global__ void k_agg2(int n) {
    int v = blockIdx.x * blockDim.x + threadIdx.x;
    if (v >= n) return;
    int st = g_off[v], en = g_off[v + 1];
    float ax = 0.f, ay = 0.f;
    for (int j = st; j < en; j += 4) {
        int rem = en - j;
        int s0 = __ldg(&g_csrc[j]);
        int s1 = (rem > 1) ? __ldg(&g_csrc[j + 1]) : s0;
        int s2 = (rem > 2) ? __ldg(&g_csrc[j + 2]) : s0;
        int s3 = (rem > 3) ? __ldg(&g_csrc[j + 3]) : s0;
        float2 x0 = *(const float2*)(g_xs + 2 * s0);
        float2 x1 = *(const float2*)(g_xs + 2 * s1);
        float2 x2 = *(const float2*)(g_xs + 2 * s2);
        float2 x3 = *(const float2*)(g_xs + 2 * s3);
        float m1 = (rem > 1) ? 1.f : 0.f;
        float m2 = (rem > 2) ? 1.f : 0.f;
        float m3 = (rem > 3) ? 1.f : 0.f;
        ax += x0.x; ay += x0.y;
        ax = fmaf(m1, x1.x, ax); ay = fmaf(m1, x1.y, ay);
        ax = fmaf(m2, x2.x, ax); ay = fmaf(m2, x2.y, ay);
        ax = fmaf(m3, x3.x, ax); ay = fmaf(m3, x3.y, ay);
    }
    float dv = g_dinv[v];
    ax += g_xs[2 * v];                   // self term (already prescaled)
    ay += g_xs[2 * v + 1];
    float4 o; o.x = dv * ax; o.y = dv * ay; o.z = dv; o.w = 0.f;
    g_ax4[v] = o;                        // (Ax)[v] plus own dinv
}

// ---------------- layer 2 aggregation with lin1 fused ----------------
// t2[v] = dinv[v] * ( sum_{s in N(v) ∪ {v}} dinv[s]*relu(W1^T (Ax)[s] + b1) )
// output TRANSPOSED [c][node]
__global__ void k_l2agg(const float* __restrict__ W1, const float* __restrict__ b1, int n) {
    __shared__ float sT[64 * 9];
    int t = threadIdx.x, wid = t >> 5, lane = t & 31;
    int v = blockIdx.x * 8 + wid;
    float w1x0 = W1[lane],      w1y0 = W1[64 + lane],  bb0 = b1[lane];
    float w1x1 = W1[lane + 32], w1y1 = W1[96 + lane],  bb1 = b1[lane + 32];
    float a0 = 0.f, a1 = 0.f;
    if (v < n) {
        int st = g_off[v], en = g_off[v + 1];
        for (int j = st; j < en; j += 4) {
            int rem = en - j;
            int s0 = __ldg(&g_csrc[j]);
            int s1 = (rem > 1) ? __ldg(&g_csrc[j + 1]) : s0;
            int s2 = (rem > 2) ? __ldg(&g_csrc[j + 2]) : s0;
            int s3 = (rem > 3) ? __ldg(&g_csrc[j + 3]) : s0;
            float4 q0 = g_ax4[s0];
            float4 q1 = g_ax4[s1];
            float4 q2 = g_ax4[s2];
            float4 q3 = g_ax4[s3];
            float m1 = (rem > 1) ? 1.f : 0.f;
            float m2 = (rem > 2) ? 1.f : 0.f;
            float m3 = (rem > 3) ? 1.f : 0.f;
            float h;
            h = fmaxf(fmaf(q0.x, w1x0, fmaf(q0.y, w1y0, bb0)), 0.f);      a0 = fmaf(q0.z, h, a0);
            h = fmaxf(fmaf(q0.x, w1x1, fmaf(q0.y, w1y1, bb1)), 0.f);      a1 = fmaf(q0.z, h, a1);
            h = fmaxf(fmaf(q1.x, w1x0, fmaf(q1.y, w1y0, bb0)), 0.f);      a0 = fmaf(m1 * q1.z, h, a0);
            h = fmaxf(fmaf(q1.x, w1x1, fmaf(q1.y, w1y1, bb1)), 0.f);      a1 = fmaf(m1 * q1.z, h, a1);
            h = fmaxf(fmaf(q2.x, w1x0, fmaf(q2.y, w1y0, bb0)), 0.f);      a0 = fmaf(m2 * q2.z, h, a0);
            h = fmaxf(fmaf(q2.x, w1x1, fmaf(q2.y, w1y1, bb1)), 0.f);      a1 = fmaf(m2 * q2.z, h, a1);
            h = fmaxf(fmaf(q3.x, w1x0, fmaf(q3.y, w1y0, bb0)), 0.f);      a0 = fmaf(m3 * q3.z, h, a0);
            h = fmaxf(fmaf(q3.x, w1x1, fmaf(q3.y, w1y1, bb1)), 0.f);      a1 = fmaf(m3 * q3.z, h, a1);
        }
        float4 q = g_ax4[v];            // self term
        float h;
        h = fmaxf(fmaf(q.x, w1x0, fmaf(q.y, w1y0, bb0)), 0.f); a0 = fmaf(q.z, h, a0);
        h = fmaxf(fmaf(q.x, w1x1, fmaf(q.y, w1y1, bb1)), 0.f); a1 = fmaf(q.z, h, a1);
        a0 *= q.z;                       // outer dinv[v]
        a1 *= q.z;
    }
    sT[lane * 9 + wid] = a0;
    sT[(lane + 32) * 9 + wid] = a1;
    __syncthreads();
    int base = blockIdx.x * 8;
    for (int q = t; q < 512; q += 256) {
        int c = q >> 3, j = q & 7;
        if (base + j < n) g_bufA[(size_t)c * NSTR + base + j] = sT[c * 9 + j];
    }
}

// ---------------- fused MLP: g2s = dinv * (relu(t2 @ W2 + b2) @ W3) -> bf16 ------
__global__ __launch_bounds__(128, 2) void k_mlp(const float* __restrict__ W2,
                                                const float* __restrict__ b2,
                                                const float* __restrict__ W3,
                                                int n) {
    extern __shared__ float sm[];
    float* sW2 = sm;                 // 64*64
    float* sW3 = sm + 4096;          // 64*64
    float* sA  = sm + 8192;          // [64][132]
    float* sB  = sA + 64 * 132;      // [64][132]
    const int t  = threadIdx.x;
    const int cg = t & 7;
    const int ng = t >> 3;

    for (int i = t; i < 1024; i += 128) {
        ((float4*)sW2)[i] = ((const float4*)W2)[i];
        ((float4*)sW3)[i] = ((const float4*)W3)[i];
    }
    u64 bias2[4];
    #pragma unroll
    for (int j = 0; j < 4; j++)
        bias2[j] = *(const u64*)(b2 + cg * 8 + 2 * j);
    __syncthreads();

    const int ntiles = (n + 127) >> 7;
    for (int tile = blockIdx.x; tile < ntiles; tile += gridDim.x) {
        const int base = tile << 7;
        for (int q = t; q < 64 * 32; q += 128) {
            int c = q >> 5, v4 = (q & 31) << 2;
            float4 val;
            if (base + v4 + 3 < n) {
                val = *(const float4*)(g_bufA + (size_t)c * NSTR + base + v4);
            } else {
                const float* p = g_bufA + (size_t)c * NSTR + base + v4;
                int rem = n - base - v4;
                val.x = (rem > 0) ? p[0] : 0.f;
                val.y = (rem > 1) ? p[1] : 0.f;
                val.z = (rem > 2) ? p[2] : 0.f;
                val.w = (rem > 3) ? p[3] : 0.f;
            }
            *(float4*)(sA + c * 132 + v4) = val;
        }
        __syncthreads();

        // GEMM1: acc = t2 @ W2 + b2
        u64 acc[8][4];
        #pragma unroll
        for (int i = 0; i < 8; i++)
            #pragma unroll
            for (int j = 0; j < 4; j++) acc[i][j] = bias2[j];
        #pragma unroll 8
        for (int k = 0; k < 64; k++) {
            float4 h0 = *(const float4*)(sA + k * 132 + ng * 8);
            float4 h1 = *(const float4*)(sA + k * 132 + ng * 8 + 4);
            u64 hh[8];
            hh[0] = pack2(h0.x, h0.x); hh[1] = pack2(h0.y, h0.y);
            hh[2] = pack2(h0.z, h0.z); hh[3] = pack2(h0.w, h0.w);
            hh[4] = pack2(h1.x, h1.x); hh[5] = pack2(h1.y, h1.y);
            hh[6] = pack2(h1.z, h1.z); hh[7] = pack2(h1.w, h1.w);
            #pragma unroll
            for (int j = 0; j < 4; j++) {
                u64 w = *(const u64*)(sW2 + k * 64 + cg * 8 + 2 * j);
                #pragma unroll
                for (int i = 0; i < 8; i++) fma2(acc[i][j], hh[i], w, acc[i][j]);
            }
        }
        // relu -> sB (k-major)
        #pragma unroll
        for (int j = 0; j < 4; j++) {
            float lo[8], hi[8];
            #pragma unroll
            for (int i = 0; i < 8; i++) {
                float a, b; unpack2(acc[i][j], a, b);
                lo[i] = fmaxf(a, 0.f); hi[i] = fmaxf(b, 0.f);
            }
            int c0 = cg * 8 + 2 * j, c1 = c0 + 1;
            *(float4*)(sB + c0 * 132 + ng * 8)     = make_float4(lo[0], lo[1], lo[2], lo[3]);
            *(float4*)(sB + c0 * 132 + ng * 8 + 4) = make_float4(lo[4], lo[5], lo[6], lo[7]);
            *(float4*)(sB + c1 * 132 + ng * 8)     = make_float4(hi[0], hi[1], hi[2], hi[3]);
            *(float4*)(sB + c1 * 132 + ng * 8 + 4) = make_float4(hi[4], hi[5], hi[6], hi[7]);
        }
        __syncthreads();

        // GEMM2: g2 = h2 @ W3 ; epilogue multiplies by dinv[node], packs bf16
        u64 acc2[8][4];
        #pragma unroll
        for (int i = 0; i < 8; i++)
            #pragma unroll
            for (int j = 0; j < 4; j++) acc2[i][j] = 0ull;
        #pragma unroll 8
        for (int k = 0; k < 64; k++) {
            float4 h0 = *(const float4*)(sB + k * 132 + ng * 8);
            float4 h1 = *(const float4*)(sB + k * 132 + ng * 8 + 4);
            u64 hh[8];
            hh[0] = pack2(h0.x, h0.x); hh[1] = pack2(h0.y, h0.y);
            hh[2] = pack2(h0.z, h0.z); hh[3] = pack2(h0.w, h0.w);
            hh[4] = pack2(h1.x, h1.x); hh[5] = pack2(h1.y, h1.y);
            hh[6] = pack2(h1.z, h1.z); hh[7] = pack2(h1.w, h1.w);
            #pragma unroll
            for (int j = 0; j < 4; j++) {
                u64 w = *(const u64*)(sW3 + k * 64 + cg * 8 + 2 * j);
                #pragma unroll
                for (int i = 0; i < 8; i++) fma2(acc2[i][j], hh[i], w, acc2[i][j]);
            }
        }
        #pragma unroll
        for (int i = 0; i < 8; i++) {
            int node = base + ng * 8 + i;
            if (node < n) {
                float dv = __ldg(&g_dinv[node]);
                unsigned r[4];
                #pragma unroll
                for (int j = 0; j < 4; j++) {
                    float a, b; unpack2(acc2[i][j], a, b);
                    r[j] = bf16pack(a * dv, b * dv);
                }
                *(uint4*)(g_bufBh + (size_t)node * 64 + cg * 8) = make_uint4(r[0], r[1], r[2], r[3]);
            }
        }
        __syncthreads();
    }
}

// ---------------- layer 3 aggregation: h3 = dinv*(sum g2s) + b3 ----------------
// warp per node; 2 edges in flight (half-warps), 16 lanes x 4 bf16 per row
__global__ void k_agg64(const float* __restrict__ b3, int n) {
    int t = threadIdx.x;
    int w = (blockIdx.x * blockDim.x + t) >> 5;
    int lane = t & 31;
    int half = lane >> 4, l16 = lane & 15;
    if (w >= n) return;
    int st = g_off[w], en = g_off[w + 1];
    float4 a = make_float4(0.f, 0.f, 0.f, 0.f);
    int j = st + half;
    int s = (j < en) ? __ldg(&g_csrc[j]) : 0;
    while (j < en) {
        int jn = j + 2;
        int sn = (jn < en) ? __ldg(&g_csrc[jn]) : 0;
        uint2 u = *(const uint2*)(g_bufBh + (size_t)s * 64 + l16 * 4);
        float2 f01 = __bfloat1622float2(*(__nv_bfloat162*)&u.x);
        float2 f23 = __bfloat1622float2(*(__nv_bfloat162*)&u.y);
        a.x += f01.x; a.y += f01.y; a.z += f23.x; a.w += f23.y;
        s = sn; j = jn;
    }
    if (half == 0) {
        uint2 u = *(const uint2*)(g_bufBh + (size_t)w * 64 + l16 * 4);  // self term
        float2 f01 = __bfloat1622float2(*(__nv_bfloat162*)&u.x);
        float2 f23 = __bfloat1622float2(*(__nv_bfloat162*)&u.y);
        a.x += f01.x; a.y += f01.y; a.z += f23.x; a.w += f23.y;
    }
    a.x += __shfl_xor_sync(0xffffffffu, a.x, 16);
    a.y += __shfl_xor_sync(0xffffffffu, a.y, 16);
    a.z += __shfl_xor_sync(0xffffffffu, a.z, 16);
    a.w += __shfl_xor_sync(0xffffffffu, a.w, 16);
    if (half == 0) {
        float dv = g_dinv[w];
        float4 bb = *(const float4*)(b3 + l16 * 4);
        a.x = fmaf(dv, a.x, bb.x); a.y = fmaf(dv, a.y, bb.y);
        a.z = fmaf(dv, a.z, bb.z); a.w = fmaf(dv, a.w, bb.w);
        *(float4*)(g_bufA + (size_t)w * 64 + l16 * 4) = a;   // h3 row-major
    }
}

// ---------------- mean pool + head (last block runs the head) ----------------
__global__ void k_poolfinal(const int* __restrict__ batch, const float* __restrict__ ge,
                            const float* __restrict__ Wl, const float* __restrict__ bl,
                            float* __restrict__ out, int n) {
    __shared__ int sb[2];
    __shared__ float red[256];
    __shared__ int s_last;
    int gid = blockIdx.x;
    int t = threadIdx.x;          // 256
    if (t < 2) {
        int target = gid + t;
        int lo = 0, hi = n;
        while (lo < hi) {
            int mid = (lo + hi) >> 1;
            if (batch[mid] < target) lo = mid + 1; else hi = mid;
        }
        sb[t] = lo;
    }
    __syncthreads();
    int s = sb[0], e = sb[1];
    int d = t & 63, str = t >> 6;
    float acc = 0.f;
    for (int nn = s + str; nn < e; nn += 4) acc += g_bufA[(size_t)nn * 64 + d];
    red[t] = acc;
    __syncthreads();
    if (t < 64) {
        float tot = red[t] + red[t + 64] + red[t + 128] + red[t + 192];
        g_pooled[gid * 64 + t] = tot / fmaxf((float)(e - s), 1.f);
    }
    __threadfence();
    if (t == 0) s_last = (atomicAdd(&g_poolctr, 1) == NGRAPH - 1);
    __syncthreads();
    if (!s_last) return;

    if (t == 0) g_poolctr = 0;    // reset for next replay
    __shared__ float sW[128 * NCLS];
    __shared__ float sbv[NCLS];
    for (int i = t; i < 128 * NCLS; i += 256) sW[i] = Wl[i];
    if (t < NCLS) sbv[t] = bl[t];
    __syncthreads();
    if (t < 128) {
        int g = t;
        float z[NCLS];
        #pragma unroll
        for (int c = 0; c < NCLS; c++) z[c] = sbv[c];
        for (int k = 0; k < 64; k++) {
            float p = g_pooled[g * HDIM + k];
            #pragma unroll
            for (int c = 0; c < NCLS; c++) z[c] = fmaf(p, sW[k * NCLS + c], z[c]);
        }
        for (int k = 0; k < 64; k++) {
            float p = ge[g * 64 + k];
            #pragma unroll
            for (int c = 0; c < NCLS; c++) z[c] = fmaf(p, sW[(64 + k) * NCLS + c], z[c]);
        }
        float m = z[0];
        #pragma unroll
        for (int c = 1; c < NCLS; c++) m = fmaxf(m, z[c]);
        float sum = 0.f;
        #pragma unroll
        for (int c = 0; c < NCLS; c++) sum += expf(z[c] - m);
        float l = m + logf(sum);
        #pragma unroll
        for (int c = 0; c < NCLS; c++) out[g * NCLS + c] = z[c] - l;
    }
}

// ---------------- launch ----------------
extern "C" void kernel_launch(void* const* d_in, const int* in_sizes, int n_in,
                              void* d_out, int out_size) {
    const float* x     = (const float*)d_in[0];
    const int*   ei    = (const int*)d_in[1];
    const int*   batch = (const int*)d_in[2];
    const float* ge    = (const float*)d_in[3];
    const float* W1    = (const float*)d_in[4];
    const float* b1    = (const float*)d_in[5];
    const float* W2    = (const float*)d_in[6];
    const float* b2    = (const float*)d_in[7];
    const float* W3    = (const float*)d_in[8];
    const float* b3    = (const float*)d_in[9];
    const float* Wl    = (const float*)d_in[10];
    const float* bl    = (const float*)d_in[11];
    float* out = (float*)d_out;

    int n  = in_sizes[0] / 2;      // x is [N,2]
    int e  = in_sizes[1] / 2;      // edge_index is [2,E]
    int nb = (n + 1023) / 1024;

    static const int mlp_smem = (4096 + 4096 + 64 * 132 * 2) * (int)sizeof(float);
    cudaFuncSetAttribute(k_mlp, cudaFuncAttributeMaxDynamicSharedMemorySize, mlp_smem);

    k_zero   <<<(n + 255) / 256, 256>>>(n);              // 0
    k_count  <<<(e + 255) / 256, 256>>>(ei + e, e);      // 1
    k_scan   <<<nb, 1024>>>(x, n);                       // 2  scan + dinv + xs + cursor
    k_scatter<<<(e + 255) / 256, 256>>>(ei, e);          // 3  lean: src only
    k_agg2   <<<(n + 127) / 128, 128>>>(n);              // 4
    k_l2agg  <<<(n + 7) / 8, 256>>>(W1, b1, n);          // 5
    k_mlp    <<<296, 128, mlp_smem>>>(W2, b2, W3, n);    // 6
    k_agg64  <<<(n + 7) / 8, 256>>>(b3, n);              // 7
    k_poolfinal<<<NGRAPH, 256>>>(batch, ge, Wl, bl, out, n); // 8
}